// round 15
// baseline (speedup 1.0000x reference)
#include <cuda_runtime.h>

typedef unsigned long long ull;

// ---------------- problem constants ----------------
#define BB   8
#define TT   8
#define CC   32
#define HH   16
#define WW   28
#define HWp  448
#define NHh  4
#define DKk  8
#define PLN  449               // smem plane stride in 16B granules (448 + zero slot)

// ---------------- device scratch ----------------
__device__ __align__(16) float g_q   [BB*TT*CC*HWp];          // [bt][o][p]
// kv plane-major: [b][h][s][plane(4)][448] float4
__device__ __align__(16) float g_kv  [BB*NHh*TT*4*HWp*4];
// tout quad-tiled: [bt][cquad(8)][p][4]  (quad = channels 4j..4j+3)
__device__ __align__(16) float g_tout[BB*TT*8*HWp*4];
// sum|mx interleaved: [bt][h][p][2]  ([0]=sum float, [1]=mx monotonic-uint)
__device__ __align__(16) unsigned g_summx[BB*TT*NHh*HWp*2];

// ---------------- packed f32x2 helpers ----------------
__device__ __forceinline__ ull pack2(float lo, float hi){ ull r; asm("mov.b64 %0,{%1,%2};":"=l"(r):"f"(lo),"f"(hi)); return r; }
__device__ __forceinline__ void unpack2(ull v, float& lo, float& hi){ asm("mov.b64 {%0,%1},%2;":"=f"(lo),"=f"(hi):"l"(v)); }
__device__ __forceinline__ ull fma2(ull a, ull b, ull c){ ull d; asm("fma.rn.f32x2 %0,%1,%2,%3;":"=l"(d):"l"(a),"l"(b),"l"(c)); return d; }
__device__ __forceinline__ ull add2(ull a, ull b){ ull d; asm("add.rn.f32x2 %0,%1,%2;":"=l"(d):"l"(a),"l"(b)); return d; }
__device__ __forceinline__ ull mul2(ull a, ull b){ ull d; asm("mul.rn.f32x2 %0,%1,%2;":"=l"(d):"l"(a),"l"(b)); return d; }
__device__ __forceinline__ float ex2f(float x){ float y; asm("ex2.approx.f32 %0,%1;":"=f"(y):"f"(x)); return y; }
__device__ __forceinline__ void red2(float* addr, float a, float b){
    asm volatile("red.global.add.v2.f32 [%0], {%1,%2};" :: "l"(addr), "f"(a), "f"(b) : "memory");
}

__device__ __forceinline__ float exp2_fast(float x) {   // k_out only
    float z = __fadd_rn(x, 12582912.0f);
    float n = __fadd_rn(z, -12582912.0f);
    float f = x - n;
    int   sb = __float_as_int(z) * 8388608 + 0x3F800000;
    float p = fmaf(fmaf(fmaf(fmaf(0.0096181291f, f, 0.055504109f),
                             f, 0.24022651f), f, 0.69314718f), f, 1.0f);
    return p * __int_as_float(sb);
}

// monotonic float->uint map
__device__ __forceinline__ unsigned fmap(float f) {
    unsigned u = __float_as_uint(f);
    return (u & 0x80000000u) ? ~u : (u | 0x80000000u);
}
__device__ __forceinline__ float funmap(unsigned m) {
    return (m & 0x80000000u) ? __uint_as_float(m ^ 0x80000000u)
                             : __uint_as_float(~m);
}

// ---------------- K1: Q/K/V projections + combine-buffer zeroing ----------------
__global__ __launch_bounds__(128)
void k_proj(const float* __restrict__ first, const float* __restrict__ x,
            const float* __restrict__ Wq, const float* __restrict__ Wk,
            const float* __restrict__ Wv) {
    __shared__ float swq[1024], swk[1024], swv[1024];
    int tid = threadIdx.x;
    for (int i = tid; i < 1024; i += 128) { swq[i]=Wq[i]; swk[i]=Wk[i]; swv[i]=Wv[i]; }

    int gi = blockIdx.x * 128 + tid;              // [0, 28672)

    // zero combine buffers (8 float4 tout + 2 uint4 summx per thread)
    {
        float4 z4 = make_float4(0.f,0.f,0.f,0.f);
        float4* t4 = (float4*)g_tout;
        #pragma unroll
        for (int j = 0; j < 8; j++) t4[gi + j*28672] = z4;
        uint4 zu = make_uint4(0u,0u,0u,0u);
        ((uint4*)g_summx)[gi]          = zu;
        ((uint4*)g_summx)[gi + 28672]  = zu;
    }
    __syncthreads();

    int p  = gi % HWp;
    int bt = gi / HWp;
    int b  = bt >> 3, t = bt & 7;

    const float* fb = first + (size_t)bt * CC * HWp + p;
    const float* xb = x     + (size_t)bt * CC * HWp + p;
    ull fp[16], xp[16];
    #pragma unroll
    for (int j = 0; j < 16; j++) {
        fp[j] = pack2(fb[(2*j)*HWp], fb[(2*j+1)*HWp]);
        xp[j] = pack2(xb[(2*j)*HWp], xb[(2*j+1)*HWp]);
    }

    #pragma unroll
    for (int h = 0; h < NHh; h++) {
        float kr[8], vr[8];
        #pragma unroll
        for (int c8 = 0; c8 < 8; c8++) {
            int o = h*8 + c8;
            const ull* wq = (const ull*)&swq[o*CC];
            const ull* wk = (const ull*)&swk[o*CC];
            const ull* wv = (const ull*)&swv[o*CC];
            ull aq = mul2(fp[0], wq[0]);
            ull ak = mul2(xp[0], wk[0]);
            ull av = mul2(xp[0], wv[0]);
            #pragma unroll
            for (int j = 1; j < 16; j++) {
                aq = fma2(fp[j], wq[j], aq);
                ak = fma2(xp[j], wk[j], ak);
                av = fma2(xp[j], wv[j], av);
            }
            float l, hh;
            unpack2(aq, l, hh);
            g_q[((size_t)bt*CC + o)*HWp + p] = l + hh;
            unpack2(ak, l, hh); kr[c8] = l + hh;
            unpack2(av, l, hh); vr[c8] = l + hh;
        }
        float4* dst = (float4*)g_kv + ((((size_t)b*NHh + h)*TT + t)*4)*HWp + p;
        dst[0*HWp] = make_float4(kr[0], kr[1], kr[2], kr[3]);
        dst[1*HWp] = make_float4(kr[4], kr[5], kr[6], kr[7]);
        dst[2*HWp] = make_float4(vr[0], vr[1], vr[2], vr[3]);
        dst[3*HWp] = make_float4(vr[4], vr[5], vr[6], vr[7]);
    }
}

// ---------------- K2: per-(b,t,head) LayerNorm of q ----------------
__global__ __launch_bounds__(128)
void k_ln(const float* __restrict__ gamma, const float* __restrict__ beta) {
    const int N = DKk * HWp;                      // 3584
    float* base = g_q + (size_t)blockIdx.x * N;
    int tid = threadIdx.x;

    float vals[28];
    float s = 0.f, sq = 0.f;
    #pragma unroll
    for (int i = 0; i < 28; i++) {
        float v = base[tid + i*128];
        vals[i] = v; s += v; sq = fmaf(v, v, sq);
    }
    #pragma unroll
    for (int o = 16; o > 0; o >>= 1) {
        s  += __shfl_xor_sync(0xFFFFFFFFu, s,  o);
        sq += __shfl_xor_sync(0xFFFFFFFFu, sq, o);
    }
    __shared__ float shs[4], shq[4];
    if ((tid & 31) == 0) { shs[tid>>5] = s; shq[tid>>5] = sq; }
    __syncthreads();
    s  = shs[0]+shs[1]+shs[2]+shs[3];
    sq = shq[0]+shq[1]+shq[2]+shq[3];

    float mu   = s * (1.0f/3584.0f);
    float var  = fmaf(-mu, mu, sq * (1.0f/3584.0f));
    float rstd = rsqrtf(var + 1e-5f);
    #pragma unroll
    for (int i = 0; i < 28; i++) {
        int idx = tid + i*128;
        base[idx] = fmaf((vals[i]-mu)*rstd, gamma[idx], beta[idx]);
    }
}

// ---------------- K3: dilated local attention (R12 config + cp.async staging) --
// grid = 2048: bid = [b(3)][ts(1)][s(3)][head(2)][ys(2)]; warp = one y-row.
__global__ __launch_bounds__(128, 4)
void k_attn() {
    int bid  = blockIdx.x;
    int ys   = bid & 3;
    int head = (bid >> 2) & 3;
    int s    = (bid >> 4) & 7;
    int ts   = (bid >> 7) & 1;
    int b    = bid >> 8;
    const int dil = 2*head + 1;

    __shared__ float4 skv[4*PLN + 4];             // 4 planes, stride 449 (+zero slot)

    int tid  = threadIdx.x;
    int row  = tid >> 5;
    int lane = tid & 31;
    bool act = lane < WW;
    int xq   = act ? lane : 27;                   // idle lanes mirror lane 27
    int y    = ys*4 + row;
    int p    = y*WW + xq;
    int t0   = ts*4;

    {   // stage via cp.async: gmem [plane(4)][448] -> smem plane stride 449
        const float4* src = (const float4*)g_kv +
            ((((size_t)b*NHh + head)*TT + s)*4)*HWp;
        unsigned sbase = (unsigned)__cvta_generic_to_shared(skv);
        #pragma unroll
        for (int r = 0; r < 14; r++) {
            int idx = tid + r*128;                // 0..1791
            int j   = idx / HWp;
            unsigned daddr = sbase + (unsigned)(idx + j) * 16u;   // == (j*449+sp)*16
            asm volatile("cp.async.cg.shared.global [%0], [%1], 16;"
                         :: "r"(daddr), "l"(src + idx) : "memory");
        }
        asm volatile("cp.async.commit_group;" ::: "memory");
        if (tid < 4) skv[tid*PLN + HWp] = make_float4(0.f,0.f,0.f,0.f);
    }

    const float INV = 0.35355339059327373f;                 // 1/sqrt(C/NH)
    const float S2C = 0.35355339059327373f * 1.4426950408889634f;
    const ull INV2 = pack2(INV, INV);

    // q c-pair packed per timestep
    ull qp[4][4];
    #pragma unroll
    for (int t = 0; t < 4; t++) {
        const float* qb = g_q + ((size_t)(b*TT + t0 + t)*CC + head*DKk)*HWp + p;
        #pragma unroll
        for (int j = 0; j < 4; j++)
            qp[t][j] = pack2(qb[(2*j)*HWp], qb[(2*j+1)*HWp]);
    }

    ull tout[4][4];
    #pragma unroll
    for (int t = 0; t < 4; t++)
        #pragma unroll
        for (int j = 0; j < 4; j++) tout[t][j] = pack2(0.f, 0.f);
    float sum0=0.f, sum1=0.f, sum2=0.f, sum3=0.f;
    float mx0=-126.f, mx1=-126.f, mx2=-126.f, mx3=-126.f;

    const ulonglong2* pk0 = (const ulonglong2*)(skv);
    const ulonglong2* pk1 = (const ulonglong2*)(skv + PLN);
    const ulonglong2* pv0 = (const ulonglong2*)(skv + 2*PLN);
    const ulonglong2* pv1 = (const ulonglong2*)(skv + 3*PLN);

    asm volatile("cp.async.wait_group 0;" ::: "memory");
    __syncthreads();

    #pragma unroll 1
    for (int oy = -3; oy <= 3; oy++) {
        int yy = y + oy*dil;
        if ((unsigned)yy >= (unsigned)HH) continue;   // warp-uniform skip
        int rb = yy * WW;
        #pragma unroll 2
        for (int i = 0; i < 7; i++) {
            int xx = xq + (i - 3)*dil;
            bool vx = (unsigned)xx < (unsigned)WW;
            int sp  = vx ? (rb + xx) : HWp;           // HWp -> zero slot (k=v=0)
            float bv = vx ? -32.f : -126.f;

            ulonglong2 k0 = pk0[sp];                  // (k0,k1),(k2,k3)
            ulonglong2 k1 = pk1[sp];                  // (k4,k5),(k6,k7)
            ulonglong2 v0 = pv0[sp];                  // (v0,v1),(v2,v3)
            ulonglong2 v1 = pv1[sp];                  // (v4,v5),(v6,v7)

            ull d0 = mul2(qp[0][0], k0.x);
            ull d1 = mul2(qp[1][0], k0.x);
            ull d2 = mul2(qp[2][0], k0.x);
            ull d3 = mul2(qp[3][0], k0.x);
            d0 = fma2(qp[0][1], k0.y, d0); d1 = fma2(qp[1][1], k0.y, d1);
            d2 = fma2(qp[2][1], k0.y, d2); d3 = fma2(qp[3][1], k0.y, d3);
            d0 = fma2(qp[0][2], k1.x, d0); d1 = fma2(qp[1][2], k1.x, d1);
            d2 = fma2(qp[2][2], k1.x, d2); d3 = fma2(qp[3][2], k1.x, d3);
            d0 = fma2(qp[0][3], k1.y, d0); d1 = fma2(qp[1][3], k1.y, d1);
            d2 = fma2(qp[2][3], k1.y, d2); d3 = fma2(qp[3][3], k1.y, d3);

            float l0,h0,l1,h1,l2,h2,l3,h3;
            unpack2(d0,l0,h0); unpack2(d1,l1,h1);
            unpack2(d2,l2,h2); unpack2(d3,l3,h3);
            float sc0 = l0+h0, sc1 = l1+h1, sc2 = l2+h2, sc3 = l3+h3;

            float a0 = fmaf(sc0, S2C, bv);
            float a1 = fmaf(sc1, S2C, bv);
            float a2 = fmaf(sc2, S2C, bv);
            float a3 = fmaf(sc3, S2C, bv);
            sum0 += ex2f(a0); sum1 += ex2f(a1);
            sum2 += ex2f(a2); sum3 += ex2f(a3);
            mx0 = fmaxf(mx0, a0); mx1 = fmaxf(mx1, a1);
            mx2 = fmaxf(mx2, a2); mx3 = fmaxf(mx3, a3);

            ull wp0 = pack2(sc0,sc0), wp1 = pack2(sc1,sc1);
            ull wp2 = pack2(sc2,sc2), wp3 = pack2(sc3,sc3);
            tout[0][0] = fma2(wp0, v0.x, tout[0][0]);
            tout[1][0] = fma2(wp1, v0.x, tout[1][0]);
            tout[2][0] = fma2(wp2, v0.x, tout[2][0]);
            tout[3][0] = fma2(wp3, v0.x, tout[3][0]);
            tout[0][1] = fma2(wp0, v0.y, tout[0][1]);
            tout[1][1] = fma2(wp1, v0.y, tout[1][1]);
            tout[2][1] = fma2(wp2, v0.y, tout[2][1]);
            tout[3][1] = fma2(wp3, v0.y, tout[3][1]);
            tout[0][2] = fma2(wp0, v1.x, tout[0][2]);
            tout[1][2] = fma2(wp1, v1.x, tout[1][2]);
            tout[2][2] = fma2(wp2, v1.x, tout[2][2]);
            tout[3][2] = fma2(wp3, v1.x, tout[3][2]);
            tout[0][3] = fma2(wp0, v1.y, tout[0][3]);
            tout[1][3] = fma2(wp1, v1.y, tout[1][3]);
            tout[2][3] = fma2(wp2, v1.y, tout[2][3]);
            tout[3][3] = fma2(wp3, v1.y, tout[3][3]);
        }
    }

    if (act) {
        float su[4] = { sum0, sum1, sum2, sum3 };
        float mxv[4] = { mx0, mx1, mx2, mx3 };
        #pragma unroll
        for (int t = 0; t < 4; t++) {
            int bt = b*TT + t0 + t;
            // tout quad layout: [bt][cquad(8)][p][4]; head owns quads h*2, h*2+1
            float* tb = g_tout + (((size_t)bt*8 + head*2)*HWp + p)*4;
            #pragma unroll
            for (int j = 0; j < 4; j++) {
                ull sc2 = mul2(tout[t][j], INV2);
                float el, eh; unpack2(sc2, el, eh);
                red2(tb + (size_t)(j>>1)*(HWp*4) + 2*(j&1), el, eh);
            }
            float* smx = (float*)g_summx + (((size_t)bt*NHh + head)*HWp + p)*2;
            atomicAdd(smx, su[t]);
            atomicMax((unsigned*)smx + 1, fmap(mxv[t]));
        }
    }
}

// ---------------- K4: M_S + output projection (smem-shared tc, 32p x 4oh) ----
// grid = 896 = 64 bt * 14 p-tiles. Block: 128 thr = 32 p-local x 4 oh-splits.
// tc tile (32p x 8 quads) loaded cooperatively once (2 LDG.128/thread) into
// smem; the 4 oh-threads of each p read from smem (29-cyc LDS, 2-way conflict)
// instead of each re-hauling 8 LDG.128 through L2.
__global__ __launch_bounds__(128)
void k_out(const float* __restrict__ Wo, float* __restrict__ out) {
    __shared__ float swo[1024];
    __shared__ ull   stc[32*17];                  // row stride 17 ull (2-way LDS)
    int tid = threadIdx.x;
    for (int i = tid; i < 1024; i += 128) swo[i] = Wo[i];

    int bb = blockIdx.x;
    int bt = bb / 14;
    int p0 = (bb - bt*14) * 32;

    {   // cooperative tc load: 256 float4 = 32p x 8 quads
        #pragma unroll
        for (int k = 0; k < 2; k++) {
            int idx = tid + k*128;                // 0..255
            int q   = idx >> 5;
            int pp  = idx & 31;
            float4 ld = *(const float4*)(g_tout + (((size_t)bt*8 + q)*HWp + p0 + pp)*4);
            stc[pp*17 + 2*q]     = pack2(ld.x, ld.y);
            stc[pp*17 + 2*q + 1] = pack2(ld.z, ld.w);
        }
    }
    __syncthreads();

    int pl = tid & 31;
    int oh = (tid >> 5) * 8;
    int p  = p0 + pl;

    ull tc2[16];
    #pragma unroll
    for (int j = 0; j < 16; j++) tc2[j] = stc[pl*17 + j];

    float MS = 0.f;
    #pragma unroll
    for (int h = 0; h < NHh; h++) {
        uint2 ld = *(const uint2*)(g_summx + (((size_t)bt*NHh + h)*HWp + p)*2);
        float s = __uint_as_float(ld.x);
        float m = funmap(ld.y);
        MS = fmaxf(MS, __fdividef(exp2_fast(m), s));
    }

    float* ob = out + (size_t)bt * CC * HWp + p;
    #pragma unroll
    for (int o = oh; o < oh + 8; o++) {
        const ull* wp = (const ull*)&swo[o*CC];
        ull acc = mul2(tc2[0], wp[0]);
        #pragma unroll
        for (int j = 1; j < 16; j++) acc = fma2(tc2[j], wp[j], acc);
        float l, h; unpack2(acc, l, h);
        ob[o*HWp] = (l + h) * MS;
    }
}

// ---------------- launcher ----------------
extern "C" void kernel_launch(void* const* d_in, const int* in_sizes, int n_in,
                              void* d_out, int out_size) {
    const float* first = (const float*)d_in[0];
    const float* x     = (const float*)d_in[1];
    const float* Wq    = (const float*)d_in[2];
    const float* Wk    = (const float*)d_in[3];
    const float* Wv    = (const float*)d_in[4];
    const float* Wo    = (const float*)d_in[5];
    const float* lng   = (const float*)d_in[6];
    const float* lnb   = (const float*)d_in[7];
    float* out = (float*)d_out;

    k_proj<<<224, 128>>>(first, x, Wq, Wk, Wv);
    k_ln<<<BB*TT*NHh, 128>>>(lng, lnb);
    k_attn<<<2048, 128>>>();
    k_out<<<896, 128>>>(Wo, out);
}

// round 16
// speedup vs baseline: 1.0336x; 1.0336x over previous
#include <cuda_runtime.h>

typedef unsigned long long ull;

// ---------------- problem constants ----------------
#define BB   8
#define TT   8
#define CC   32
#define HH   16
#define WW   28
#define HWp  448
#define NHh  4
#define DKk  8
#define PLN  449               // smem plane stride in 16B granules (448 + zero slot)

// ---------------- device scratch ----------------
__device__ __align__(16) float g_q   [BB*TT*CC*HWp];          // [bt][o][p]
// kv plane-major: [b][h][s][plane(4)][448] float4
__device__ __align__(16) float g_kv  [BB*NHh*TT*4*HWp*4];
// tout quad-tiled: [bt][cquad(8)][p][4]  (quad = channels 4j..4j+3)
__device__ __align__(16) float g_tout[BB*TT*8*HWp*4];
// sum|mx interleaved: [bt][h][p][2]  ([0]=sum float, [1]=mx monotonic-uint)
__device__ __align__(16) unsigned g_summx[BB*TT*NHh*HWp*2];

// ---------------- packed f32x2 helpers ----------------
__device__ __forceinline__ ull pack2(float lo, float hi){ ull r; asm("mov.b64 %0,{%1,%2};":"=l"(r):"f"(lo),"f"(hi)); return r; }
__device__ __forceinline__ void unpack2(ull v, float& lo, float& hi){ asm("mov.b64 {%0,%1},%2;":"=f"(lo),"=f"(hi):"l"(v)); }
__device__ __forceinline__ ull fma2(ull a, ull b, ull c){ ull d; asm("fma.rn.f32x2 %0,%1,%2,%3;":"=l"(d):"l"(a),"l"(b),"l"(c)); return d; }
__device__ __forceinline__ ull add2(ull a, ull b){ ull d; asm("add.rn.f32x2 %0,%1,%2;":"=l"(d):"l"(a),"l"(b)); return d; }
__device__ __forceinline__ ull mul2(ull a, ull b){ ull d; asm("mul.rn.f32x2 %0,%1,%2;":"=l"(d):"l"(a),"l"(b)); return d; }
__device__ __forceinline__ float ex2f(float x){ float y; asm("ex2.approx.f32 %0,%1;":"=f"(y):"f"(x)); return y; }
__device__ __forceinline__ void red2(float* addr, float a, float b){
    asm volatile("red.global.add.v2.f32 [%0], {%1,%2};" :: "l"(addr), "f"(a), "f"(b) : "memory");
}

__device__ __forceinline__ float exp2_fast(float x) {   // k_out only
    float z = __fadd_rn(x, 12582912.0f);
    float n = __fadd_rn(z, -12582912.0f);
    float f = x - n;
    int   sb = __float_as_int(z) * 8388608 + 0x3F800000;
    float p = fmaf(fmaf(fmaf(fmaf(0.0096181291f, f, 0.055504109f),
                             f, 0.24022651f), f, 0.69314718f), f, 1.0f);
    return p * __int_as_float(sb);
}

// monotonic float->uint map
__device__ __forceinline__ unsigned fmap(float f) {
    unsigned u = __float_as_uint(f);
    return (u & 0x80000000u) ? ~u : (u | 0x80000000u);
}
__device__ __forceinline__ float funmap(unsigned m) {
    return (m & 0x80000000u) ? __uint_as_float(m ^ 0x80000000u)
                             : __uint_as_float(~m);
}

// ---------------- K1: Q/K/V projections + combine-buffer zeroing ----------------
__global__ __launch_bounds__(128)
void k_proj(const float* __restrict__ first, const float* __restrict__ x,
            const float* __restrict__ Wq, const float* __restrict__ Wk,
            const float* __restrict__ Wv) {
    __shared__ float swq[1024], swk[1024], swv[1024];
    int tid = threadIdx.x;
    for (int i = tid; i < 1024; i += 128) { swq[i]=Wq[i]; swk[i]=Wk[i]; swv[i]=Wv[i]; }

    int gi = blockIdx.x * 128 + tid;              // [0, 28672)

    // zero combine buffers (8 float4 tout + 2 uint4 summx per thread)
    {
        float4 z4 = make_float4(0.f,0.f,0.f,0.f);
        float4* t4 = (float4*)g_tout;
        #pragma unroll
        for (int j = 0; j < 8; j++) t4[gi + j*28672] = z4;
        uint4 zu = make_uint4(0u,0u,0u,0u);
        ((uint4*)g_summx)[gi]          = zu;
        ((uint4*)g_summx)[gi + 28672]  = zu;
    }
    __syncthreads();

    int p  = gi % HWp;
    int bt = gi / HWp;
    int b  = bt >> 3, t = bt & 7;

    const float* fb = first + (size_t)bt * CC * HWp + p;
    const float* xb = x     + (size_t)bt * CC * HWp + p;
    ull fp[16], xp[16];
    #pragma unroll
    for (int j = 0; j < 16; j++) {
        fp[j] = pack2(fb[(2*j)*HWp], fb[(2*j+1)*HWp]);
        xp[j] = pack2(xb[(2*j)*HWp], xb[(2*j+1)*HWp]);
    }

    #pragma unroll
    for (int h = 0; h < NHh; h++) {
        float kr[8], vr[8];
        #pragma unroll
        for (int c8 = 0; c8 < 8; c8++) {
            int o = h*8 + c8;
            const ull* wq = (const ull*)&swq[o*CC];
            const ull* wk = (const ull*)&swk[o*CC];
            const ull* wv = (const ull*)&swv[o*CC];
            ull aq = mul2(fp[0], wq[0]);
            ull ak = mul2(xp[0], wk[0]);
            ull av = mul2(xp[0], wv[0]);
            #pragma unroll
            for (int j = 1; j < 16; j++) {
                aq = fma2(fp[j], wq[j], aq);
                ak = fma2(xp[j], wk[j], ak);
                av = fma2(xp[j], wv[j], av);
            }
            float l, hh;
            unpack2(aq, l, hh);
            g_q[((size_t)bt*CC + o)*HWp + p] = l + hh;
            unpack2(ak, l, hh); kr[c8] = l + hh;
            unpack2(av, l, hh); vr[c8] = l + hh;
        }
        float4* dst = (float4*)g_kv + ((((size_t)b*NHh + h)*TT + t)*4)*HWp + p;
        dst[0*HWp] = make_float4(kr[0], kr[1], kr[2], kr[3]);
        dst[1*HWp] = make_float4(kr[4], kr[5], kr[6], kr[7]);
        dst[2*HWp] = make_float4(vr[0], vr[1], vr[2], vr[3]);
        dst[3*HWp] = make_float4(vr[4], vr[5], vr[6], vr[7]);
    }
}

// ---------------- K2: per-(b,t,head) LayerNorm of q ----------------
__global__ __launch_bounds__(128)
void k_ln(const float* __restrict__ gamma, const float* __restrict__ beta) {
    const int N = DKk * HWp;                      // 3584
    float* base = g_q + (size_t)blockIdx.x * N;
    int tid = threadIdx.x;

    float vals[28];
    float s = 0.f, sq = 0.f;
    #pragma unroll
    for (int i = 0; i < 28; i++) {
        float v = base[tid + i*128];
        vals[i] = v; s += v; sq = fmaf(v, v, sq);
    }
    #pragma unroll
    for (int o = 16; o > 0; o >>= 1) {
        s  += __shfl_xor_sync(0xFFFFFFFFu, s,  o);
        sq += __shfl_xor_sync(0xFFFFFFFFu, sq, o);
    }
    __shared__ float shs[4], shq[4];
    if ((tid & 31) == 0) { shs[tid>>5] = s; shq[tid>>5] = sq; }
    __syncthreads();
    s  = shs[0]+shs[1]+shs[2]+shs[3];
    sq = shq[0]+shq[1]+shq[2]+shq[3];

    float mu   = s * (1.0f/3584.0f);
    float var  = fmaf(-mu, mu, sq * (1.0f/3584.0f));
    float rstd = rsqrtf(var + 1e-5f);
    #pragma unroll
    for (int i = 0; i < 28; i++) {
        int idx = tid + i*128;
        base[idx] = fmaf((vals[i]-mu)*rstd, gamma[idx], beta[idx]);
    }
}

// ---------------- K3: dilated local attention (verified-best R12 config) ------
// grid = 2048: bid = [b(3)][ts(1)][s(3)][head(2)][ys(2)]; warp = one y-row
// (warp-uniform oy skip). Plane-major smem, c-pair k (4 LDS.128/offset),
// MUFU ex2 softmax, quad-tiled v2-RED combine tail. 3.5 waves of blocks
// gives work-stealing balance across the 2.6x per-head work spread.
__global__ __launch_bounds__(128, 4)
void k_attn() {
    int bid  = blockIdx.x;
    int ys   = bid & 3;
    int head = (bid >> 2) & 3;
    int s    = (bid >> 4) & 7;
    int ts   = (bid >> 7) & 1;
    int b    = bid >> 8;
    const int dil = 2*head + 1;

    __shared__ float4 skv[4*PLN + 4];             // 4 planes, stride 449 (+zero slot)

    int tid  = threadIdx.x;
    int row  = tid >> 5;
    int lane = tid & 31;
    bool act = lane < WW;
    int xq   = act ? lane : 27;                   // idle lanes mirror lane 27
    int y    = ys*4 + row;
    int p    = y*WW + xq;
    int t0   = ts*4;

    {   // stage: gmem [plane(4)][448] -> smem plane stride 449
        const float4* src = (const float4*)g_kv +
            ((((size_t)b*NHh + head)*TT + s)*4)*HWp;
        #pragma unroll
        for (int r = 0; r < 14; r++) {
            int idx = tid + r*128;                // 0..1791
            int j   = idx / HWp;
            skv[idx + j] = src[idx];              // == j*449 + sp
        }
        if (tid < 4) skv[tid*PLN + HWp] = make_float4(0.f,0.f,0.f,0.f);
    }

    const float INV = 0.35355339059327373f;                 // 1/sqrt(C/NH)
    const float S2C = 0.35355339059327373f * 1.4426950408889634f;
    const ull INV2 = pack2(INV, INV);

    // q c-pair packed per timestep
    ull qp[4][4];
    #pragma unroll
    for (int t = 0; t < 4; t++) {
        const float* qb = g_q + ((size_t)(b*TT + t0 + t)*CC + head*DKk)*HWp + p;
        #pragma unroll
        for (int j = 0; j < 4; j++)
            qp[t][j] = pack2(qb[(2*j)*HWp], qb[(2*j+1)*HWp]);
    }

    ull tout[4][4];
    #pragma unroll
    for (int t = 0; t < 4; t++)
        #pragma unroll
        for (int j = 0; j < 4; j++) tout[t][j] = pack2(0.f, 0.f);
    float sum0=0.f, sum1=0.f, sum2=0.f, sum3=0.f;
    float mx0=-126.f, mx1=-126.f, mx2=-126.f, mx3=-126.f;

    const ulonglong2* pk0 = (const ulonglong2*)(skv);
    const ulonglong2* pk1 = (const ulonglong2*)(skv + PLN);
    const ulonglong2* pv0 = (const ulonglong2*)(skv + 2*PLN);
    const ulonglong2* pv1 = (const ulonglong2*)(skv + 3*PLN);
    __syncthreads();

    #pragma unroll 1
    for (int oy = -3; oy <= 3; oy++) {
        int yy = y + oy*dil;
        if ((unsigned)yy >= (unsigned)HH) continue;   // warp-uniform skip
        int rb = yy * WW;
        #pragma unroll 2
        for (int i = 0; i < 7; i++) {
            int xx = xq + (i - 3)*dil;
            bool vx = (unsigned)xx < (unsigned)WW;
            int sp  = vx ? (rb + xx) : HWp;           // HWp -> zero slot (k=v=0)
            float bv = vx ? -32.f : -126.f;

            ulonglong2 k0 = pk0[sp];                  // (k0,k1),(k2,k3)
            ulonglong2 k1 = pk1[sp];                  // (k4,k5),(k6,k7)
            ulonglong2 v0 = pv0[sp];                  // (v0,v1),(v2,v3)
            ulonglong2 v1 = pv1[sp];                  // (v4,v5),(v6,v7)

            ull d0 = mul2(qp[0][0], k0.x);
            ull d1 = mul2(qp[1][0], k0.x);
            ull d2 = mul2(qp[2][0], k0.x);
            ull d3 = mul2(qp[3][0], k0.x);
            d0 = fma2(qp[0][1], k0.y, d0); d1 = fma2(qp[1][1], k0.y, d1);
            d2 = fma2(qp[2][1], k0.y, d2); d3 = fma2(qp[3][1], k0.y, d3);
            d0 = fma2(qp[0][2], k1.x, d0); d1 = fma2(qp[1][2], k1.x, d1);
            d2 = fma2(qp[2][2], k1.x, d2); d3 = fma2(qp[3][2], k1.x, d3);
            d0 = fma2(qp[0][3], k1.y, d0); d1 = fma2(qp[1][3], k1.y, d1);
            d2 = fma2(qp[2][3], k1.y, d2); d3 = fma2(qp[3][3], k1.y, d3);

            float l0,h0,l1,h1,l2,h2,l3,h3;
            unpack2(d0,l0,h0); unpack2(d1,l1,h1);
            unpack2(d2,l2,h2); unpack2(d3,l3,h3);
            float sc0 = l0+h0, sc1 = l1+h1, sc2 = l2+h2, sc3 = l3+h3;

            float a0 = fmaf(sc0, S2C, bv);
            float a1 = fmaf(sc1, S2C, bv);
            float a2 = fmaf(sc2, S2C, bv);
            float a3 = fmaf(sc3, S2C, bv);
            sum0 += ex2f(a0); sum1 += ex2f(a1);
            sum2 += ex2f(a2); sum3 += ex2f(a3);
            mx0 = fmaxf(mx0, a0); mx1 = fmaxf(mx1, a1);
            mx2 = fmaxf(mx2, a2); mx3 = fmaxf(mx3, a3);

            ull wp0 = pack2(sc0,sc0), wp1 = pack2(sc1,sc1);
            ull wp2 = pack2(sc2,sc2), wp3 = pack2(sc3,sc3);
            tout[0][0] = fma2(wp0, v0.x, tout[0][0]);
            tout[1][0] = fma2(wp1, v0.x, tout[1][0]);
            tout[2][0] = fma2(wp2, v0.x, tout[2][0]);
            tout[3][0] = fma2(wp3, v0.x, tout[3][0]);
            tout[0][1] = fma2(wp0, v0.y, tout[0][1]);
            tout[1][1] = fma2(wp1, v0.y, tout[1][1]);
            tout[2][1] = fma2(wp2, v0.y, tout[2][1]);
            tout[3][1] = fma2(wp3, v0.y, tout[3][1]);
            tout[0][2] = fma2(wp0, v1.x, tout[0][2]);
            tout[1][2] = fma2(wp1, v1.x, tout[1][2]);
            tout[2][2] = fma2(wp2, v1.x, tout[2][2]);
            tout[3][2] = fma2(wp3, v1.x, tout[3][2]);
            tout[0][3] = fma2(wp0, v1.y, tout[0][3]);
            tout[1][3] = fma2(wp1, v1.y, tout[1][3]);
            tout[2][3] = fma2(wp2, v1.y, tout[2][3]);
            tout[3][3] = fma2(wp3, v1.y, tout[3][3]);
        }
    }

    if (act) {
        float su[4] = { sum0, sum1, sum2, sum3 };
        float mxv[4] = { mx0, mx1, mx2, mx3 };
        #pragma unroll
        for (int t = 0; t < 4; t++) {
            int bt = b*TT + t0 + t;
            // tout quad layout: [bt][cquad(8)][p][4]; head owns quads h*2, h*2+1
            float* tb = g_tout + (((size_t)bt*8 + head*2)*HWp + p)*4;
            #pragma unroll
            for (int j = 0; j < 4; j++) {
                ull sc2 = mul2(tout[t][j], INV2);
                float el, eh; unpack2(sc2, el, eh);
                // quad q = j>>1 at stride HWp*4; pair within quad at +2*(j&1)
                red2(tb + (size_t)(j>>1)*(HWp*4) + 2*(j&1), el, eh);
            }
            float* smx = (float*)g_summx + (((size_t)bt*NHh + head)*HWp + p)*2;
            atomicAdd(smx, su[t]);
            atomicMax((unsigned*)smx + 1, fmap(mxv[t]));
        }
    }
}

// ---------------- K4: M_S + output projection (o split 4 ways) ----------------
__global__ __launch_bounds__(128)
void k_out(const float* __restrict__ Wo, float* __restrict__ out) {
    __shared__ float swo[1024];
    int tid = threadIdx.x;
    for (int i = tid; i < 1024; i += 128) swo[i] = Wo[i];
    __syncthreads();

    int gi = blockIdx.x * 128 + tid;              // [0, 114688)
    int p  = gi % HWp;
    int r  = gi / HWp;                            // [0, 256)
    int bt = r >> 2;
    int oh = (r & 3) * 8;

    ull tc2[16];
    #pragma unroll
    for (int q = 0; q < 8; q++) {
        float4 ld = *(const float4*)(g_tout + (((size_t)bt*8 + q)*HWp + p)*4);
        tc2[2*q]   = pack2(ld.x, ld.y);
        tc2[2*q+1] = pack2(ld.z, ld.w);
    }

    float MS = 0.f;
    #pragma unroll
    for (int h = 0; h < NHh; h++) {
        uint2 ld = *(const uint2*)(g_summx + (((size_t)bt*NHh + h)*HWp + p)*2);
        float s = __uint_as_float(ld.x);
        float m = funmap(ld.y);
        MS = fmaxf(MS, __fdividef(exp2_fast(m), s));
    }

    float* ob = out + (size_t)bt * CC * HWp + p;
    #pragma unroll
    for (int o = oh; o < oh + 8; o++) {
        const ull* wp = (const ull*)&swo[o*CC];
        ull acc = mul2(tc2[0], wp[0]);
        #pragma unroll
        for (int j = 1; j < 16; j++) acc = fma2(tc2[j], wp[j], acc);
        float l, h; unpack2(acc, l, h);
        ob[o*HWp] = (l + h) * MS;
    }
}

// ---------------- launcher ----------------
extern "C" void kernel_launch(void* const* d_in, const int* in_sizes, int n_in,
                              void* d_out, int out_size) {
    const float* first = (const float*)d_in[0];
    const float* x     = (const float*)d_in[1];
    const float* Wq    = (const float*)d_in[2];
    const float* Wk    = (const float*)d_in[3];
    const float* Wv    = (const float*)d_in[4];
    const float* Wo    = (const float*)d_in[5];
    const float* lng   = (const float*)d_in[6];
    const float* lnb   = (const float*)d_in[7];
    float* out = (float*)d_out;

    k_proj<<<224, 128>>>(first, x, Wq, Wk, Wv);
    k_ln<<<BB*TT*NHh, 128>>>(lng, lnb);
    k_attn<<<2048, 128>>>();
    k_out<<<896, 128>>>(Wo, out);
}